// round 15
// baseline (speedup 1.0000x reference)
#include <cuda_runtime.h>
#include <cuda_bf16.h>
#include <cuda_fp16.h>
#include <mma.h>
#include <cstdint>

#define N_NODES 100000
#define N_PAD   100096            // 1564 * 64, lets tail tile store unguarded
#define N_TILES (N_PAD / 64)      // 1564
#define N_EDGES 1600000
#define D 128
#define GEMM_GRID 296             // 2 CTAs/SM * 148 SMs (persistent)
#define SCAN_BLK 1024
#define N_SCAN_BLOCKS ((N_NODES + SCAN_BLK - 1) / SCAN_BLK)   // 98

using namespace nvcuda;

// Device scratch (allocation-rule-compliant __device__ globals)
__device__ __half2        g_support_h[(size_t)N_PAD * 64]; // fp16 support, 25.6 MB
__device__ int            g_count[N_NODES];
__device__ int            g_cursor[N_NODES];
__device__ int            g_rowstart[N_NODES + 1];
__device__ int            g_blocksum[N_SCAN_BLOCKS];
__device__ long long      g_csr_pair[N_EDGES];            // packed (val<<32 | col)
// B split images, [k][n] row-major bf16 (wmma matrix_b row_major layout)
__device__ __nv_bfloat16  g_Bhi[128 * 128];
__device__ __nv_bfloat16  g_Blo[128 * 128];

// ---------------------------------------------------------------------------
// Prep: split W into hi/lo bf16 images, zero count/cursor, seed rowstart end.
// ---------------------------------------------------------------------------
__global__ void prep_kernel(const float* __restrict__ W) {
    int idx = blockIdx.x * blockDim.x + threadIdx.x;
    if (idx < 128 * 128) {
        float x = W[idx];                   // W is already [k][n]
        __nv_bfloat16 hi = __float2bfloat16(x);
        __nv_bfloat16 lo = __float2bfloat16(x - __bfloat162float(hi));
        g_Bhi[idx] = hi;
        g_Blo[idx] = lo;
    }
    if (idx < N_NODES) {
        g_count[idx] = 0;
        g_cursor[idx] = 0;
    }
    if (idx == 0) g_rowstart[N_NODES] = N_EDGES;  // scan total is a constant
}

// ---------------------------------------------------------------------------
// Persistent fused kernel: GEMM (split-bf16, B loaded once/CTA) + histogram.
// Epilogue converts fp32 accum -> fp16 support (halves downstream traffic).
// CTA: 256 threads = 8 warps, M-tile 64, warp tile 32x32. SMEM 104448 B.
// ---------------------------------------------------------------------------
#define STR 136
#define AHI_OFF 0
#define ALO_OFF (64 * STR)
#define BHI_OFF (128 * STR)
#define BLO_OFF (256 * STR)
#define SM_BYTES ((384 * STR) * 2)           // 104448
#define EPI_STRF 136                         // epilogue fp32 staging (A region)

__global__ __launch_bounds__(256, 2) void gemm_hist_kernel(const float* __restrict__ A,
                                                           const int* __restrict__ edge_row) {
    extern __shared__ __nv_bfloat16 sm[];
    float* smf = reinterpret_cast<float*>(sm);   // epilogue view (same bytes)
    const int tid = threadIdx.x;
    const int wid = tid >> 5;

    // --- Load B splits into SMEM ONCE. 8 uint4 per image/thread. ---
#pragma unroll
    for (int it = 0; it < 8; it++) {
        int v = it * 256 + tid;              // 0..2047
        int row = v >> 4;                    // 0..127
        int chunk = (v & 15) * 8;            // 0..120
        uint4 h = *reinterpret_cast<const uint4*>(g_Bhi + row * 128 + chunk);
        uint4 l = *reinterpret_cast<const uint4*>(g_Blo + row * 128 + chunk);
        *reinterpret_cast<uint4*>(sm + BHI_OFF + row * STR + chunk) = h;
        *reinterpret_cast<uint4*>(sm + BLO_OFF + row * STR + chunk) = l;
    }

    const int wm = (wid & 1) * 32;
    const int wn = (wid >> 1) * 32;

    for (int tile = blockIdx.x; tile < N_TILES; tile += gridDim.x) {
        const int blockM = tile * 64;

        __syncthreads();   // prior iter's epilogue SMEM reads done; B visible (1st iter)

        // --- Convert A tile fp32 -> (hi,lo) bf16 into SMEM. 8 float4/thread. ---
#pragma unroll
        for (int it = 0; it < 8; it++) {
            int linear = it * 256 + tid;     // 0..2047
            int row = linear >> 5;           // 0..63
            int kq = (linear & 31) << 2;     // 0,4,...,124
            int gr = blockM + row;
            float4 v = make_float4(0.f, 0.f, 0.f, 0.f);
            if (gr < N_NODES)
                v = *reinterpret_cast<const float4*>(A + (size_t)gr * D + kq);

            __nv_bfloat16 h0 = __float2bfloat16(v.x), h1 = __float2bfloat16(v.y);
            __nv_bfloat16 h2 = __float2bfloat16(v.z), h3 = __float2bfloat16(v.w);
            __nv_bfloat16 l0 = __float2bfloat16(v.x - __bfloat162float(h0));
            __nv_bfloat16 l1 = __float2bfloat16(v.y - __bfloat162float(h1));
            __nv_bfloat16 l2 = __float2bfloat16(v.z - __bfloat162float(h2));
            __nv_bfloat16 l3 = __float2bfloat16(v.w - __bfloat162float(h3));

            __nv_bfloat16* ah = sm + AHI_OFF + row * STR + kq;
            __nv_bfloat16* al = sm + ALO_OFF + row * STR + kq;
            *reinterpret_cast<__nv_bfloat162*>(ah)     = __nv_bfloat162(h0, h1);
            *reinterpret_cast<__nv_bfloat162*>(ah + 2) = __nv_bfloat162(h2, h3);
            *reinterpret_cast<__nv_bfloat162*>(al)     = __nv_bfloat162(l0, l1);
            *reinterpret_cast<__nv_bfloat162*>(al + 2) = __nv_bfloat162(l2, l3);
        }
        __syncthreads();

        // --- Warp-tiled MMA, 3 precision sweeps ---
        wmma::fragment<wmma::accumulator, 16, 16, 16, float> acc[2][2];
#pragma unroll
        for (int i = 0; i < 2; i++)
#pragma unroll
            for (int j = 0; j < 2; j++) wmma::fill_fragment(acc[i][j], 0.0f);

#pragma unroll
        for (int sweep = 0; sweep < 3; sweep++) {
            const __nv_bfloat16* As = sm + ((sweep == 2) ? ALO_OFF : AHI_OFF);
            const __nv_bfloat16* Bs = sm + ((sweep == 1) ? BLO_OFF : BHI_OFF);
#pragma unroll
            for (int k0 = 0; k0 < 128; k0 += 16) {
                wmma::fragment<wmma::matrix_a, 16, 16, 16, __nv_bfloat16, wmma::row_major> af[2];
                wmma::fragment<wmma::matrix_b, 16, 16, 16, __nv_bfloat16, wmma::row_major> bf[2];
#pragma unroll
                for (int i = 0; i < 2; i++)
                    wmma::load_matrix_sync(af[i], As + (wm + i * 16) * STR + k0, STR);
#pragma unroll
                for (int j = 0; j < 2; j++)
                    wmma::load_matrix_sync(bf[j], Bs + k0 * STR + wn + j * 16, STR);
#pragma unroll
                for (int i = 0; i < 2; i++)
#pragma unroll
                    for (int j = 0; j < 2; j++)
                        wmma::mma_sync(acc[i][j], af[i], bf[j], acc[i][j]);
            }
        }

        // --- Epilogue: stage fp32 in SMEM, convert to fp16, coalesced STG ---
        __syncthreads();     // all warps done reading A region
#pragma unroll
        for (int i = 0; i < 2; i++)
#pragma unroll
            for (int j = 0; j < 2; j++)
                wmma::store_matrix_sync(smf + (wm + i * 16) * EPI_STRF + wn + j * 16,
                                        acc[i][j], EPI_STRF, wmma::mem_row_major);
        __syncthreads();

        // 64 rows x 32 uint2 (4 halves each) = 2048; 8 per thread, coalesced.
#pragma unroll
        for (int it = 0; it < 8; it++) {
            int v = it * 256 + tid;          // 0..2047
            int row = v >> 5;                // 0..63
            int q = v & 31;                  // uint2 index in row
            const float* src = smf + row * EPI_STRF + q * 4;
            __half2 h0 = __floats2half2_rn(src[0], src[1]);
            __half2 h1 = __floats2half2_rn(src[2], src[3]);
            uint2 o;
            o.x = *reinterpret_cast<unsigned int*>(&h0);
            o.y = *reinterpret_cast<unsigned int*>(&h1);
            *(reinterpret_cast<uint2*>(g_support_h + (size_t)(tile * 64 + row) * 64) + q) = o;
        }
    }

    // --- Phase B: histogram (independent of GEMM output) ---
    for (int e = blockIdx.x * 256 + tid; e < N_EDGES; e += gridDim.x * 256)
        atomicAdd(&g_count[edge_row[e]], 1);
}

// ---------------------------------------------------------------------------
// Scan: per-block local scan, then addoff (block prefix computed in-kernel)
// ---------------------------------------------------------------------------
__global__ __launch_bounds__(SCAN_BLK) void scan_local_kernel() {
    __shared__ int warp_sums[32];
    const int tid = threadIdx.x;
    const int lane = tid & 31;
    const int wid = tid >> 5;
    const int i = blockIdx.x * SCAN_BLK + tid;

    int x = (i < N_NODES) ? g_count[i] : 0;
    int v = x;
#pragma unroll
    for (int o = 1; o < 32; o <<= 1) {
        int t = __shfl_up_sync(0xFFFFFFFFu, v, o);
        if (lane >= o) v += t;
    }
    if (lane == 31) warp_sums[wid] = v;
    __syncthreads();
    if (tid < 32) {
        int w = warp_sums[tid];
#pragma unroll
        for (int o = 1; o < 32; o <<= 1) {
            int t = __shfl_up_sync(0xFFFFFFFFu, w, o);
            if (tid >= o) w += t;
        }
        warp_sums[tid] = w;
    }
    __syncthreads();
    int incl = v + (wid > 0 ? warp_sums[wid - 1] : 0);
    if (i < N_NODES) g_rowstart[i] = incl - x;
    if (tid == SCAN_BLK - 1) g_blocksum[blockIdx.x] = incl;
}

// Each block computes its own prefix over the (<=98) block sums, then adds.
__global__ __launch_bounds__(SCAN_BLK) void scan_addoff_kernel() {
    __shared__ int s_off;
    const int tid = threadIdx.x;
    if (tid < 32) {
        int sum = 0;
        for (int b = tid; b < (int)blockIdx.x; b += 32) sum += g_blocksum[b];
#pragma unroll
        for (int o = 16; o > 0; o >>= 1) sum += __shfl_down_sync(0xFFFFFFFFu, sum, o);
        if (tid == 0) s_off = sum;
    }
    __syncthreads();
    const int i = blockIdx.x * SCAN_BLK + tid;
    if (i < N_NODES) g_rowstart[i] += s_off;
}

// Fill CSR as packed 8-byte (val,col) pairs: one scattered STG.64 per edge.
__global__ void fill_kernel(const float* __restrict__ edge_val,
                            const int* __restrict__ edge_row,
                            const int* __restrict__ edge_col) {
    int e = blockIdx.x * blockDim.x + threadIdx.x;
    if (e < N_EDGES) {
        int r = edge_row[e];
        int p = g_rowstart[r] + atomicAdd(&g_cursor[r], 1);
        long long pair = ((long long)(unsigned int)__float_as_uint(edge_val[e]) << 32)
                       | (unsigned int)edge_col[e];
        g_csr_pair[p] = pair;
    }
}

// ---------------------------------------------------------------------------
// Gather: one warp per output row, fp16 support rows (256 B/edge instead of
// 512 B). Lane l loads uint2 = 4 halves -> 4 fp32 accumulators. ReLU; store.
// ---------------------------------------------------------------------------
__global__ __launch_bounds__(256) void gather_kernel(float* __restrict__ out) {
    int row = blockIdx.x * 8 + (threadIdx.x >> 5);
    int lane = threadIdx.x & 31;
    if (row >= N_NODES) return;

    int s = g_rowstart[row];
    int e = g_rowstart[row + 1];

    float4 acc = make_float4(0.f, 0.f, 0.f, 0.f);
#pragma unroll 4
    for (int i = s; i < e; i++) {
        long long pair = g_csr_pair[i];
        int c = (int)(unsigned int)(pair & 0xffffffffLL);
        float v = __uint_as_float((unsigned int)((unsigned long long)pair >> 32));
        uint2 hv = *(reinterpret_cast<const uint2*>(g_support_h + (size_t)c * 64) + lane);
        __half2 a = *reinterpret_cast<__half2*>(&hv.x);
        __half2 b = *reinterpret_cast<__half2*>(&hv.y);
        float2 fa = __half22float2(a);
        float2 fb = __half22float2(b);
        acc.x = fmaf(v, fa.x, acc.x);
        acc.y = fmaf(v, fa.y, acc.y);
        acc.z = fmaf(v, fb.x, acc.z);
        acc.w = fmaf(v, fb.y, acc.w);
    }

    acc.x = fmaxf(acc.x, 0.f);
    acc.y = fmaxf(acc.y, 0.f);
    acc.z = fmaxf(acc.z, 0.f);
    acc.w = fmaxf(acc.w, 0.f);
    *reinterpret_cast<float4*>(out + (size_t)row * D + lane * 4) = acc;
}

extern "C" void kernel_launch(void* const* d_in, const int* in_sizes, int n_in,
                              void* d_out, int out_size) {
    const float* features = (const float*)d_in[0];   // [100000, 128]
    const float* weight   = (const float*)d_in[1];   // [128, 128]
    const float* edge_val = (const float*)d_in[2];   // [1600000]
    const int*   edge_row = (const int*)d_in[3];     // [1600000]
    const int*   edge_col = (const int*)d_in[4];     // [1600000]
    float* out = (float*)d_out;                      // [100000, 128]

    cudaFuncSetAttribute(gemm_hist_kernel,
                         cudaFuncAttributeMaxDynamicSharedMemorySize, SM_BYTES);

    // 1) prep (B split + counter zeroing + rowstart end)
    prep_kernel<<<(N_NODES + 255) / 256, 256>>>(weight);

    // 2) persistent fused GEMM + histogram
    gemm_hist_kernel<<<GEMM_GRID, 256, SM_BYTES>>>(features, edge_row);

    // 3) scan + fill
    scan_local_kernel<<<N_SCAN_BLOCKS, SCAN_BLK>>>();
    scan_addoff_kernel<<<N_SCAN_BLOCKS, SCAN_BLK>>>();
    fill_kernel<<<(N_EDGES + 255) / 256, 256>>>(edge_val, edge_row, edge_col);

    // 4) fused gather + ReLU -> out
    gather_kernel<<<(N_NODES + 7) / 8, 256>>>(out);
}

// round 16
// speedup vs baseline: 1.4437x; 1.4437x over previous
#include <cuda_runtime.h>
#include <cuda_bf16.h>
#include <cuda_fp16.h>
#include <mma.h>
#include <cstdint>

#define N_NODES 100000
#define N_PAD   100096            // 1564 * 64, lets tail tile store unguarded
#define N_TILES (N_PAD / 64)      // 1564
#define N_EDGES 1600000
#define D 128
#define GEMM_GRID 296             // 2 CTAs/SM * 148 SMs (persistent)
#define SCAN_BLK 1024
#define N_SCAN_BLOCKS ((N_NODES + SCAN_BLK - 1) / SCAN_BLK)   // 98

using namespace nvcuda;

// Device scratch (allocation-rule-compliant __device__ globals)
__device__ __half2        g_support_h[(size_t)N_PAD * 64]; // fp16 support, 25.6 MB
__device__ int            g_count[N_NODES];
__device__ int            g_cursor[N_NODES];
__device__ int            g_rowstart[N_NODES + 1];
__device__ int            g_blocksum[N_SCAN_BLOCKS];
__device__ long long      g_csr_pair[N_EDGES];            // packed (val<<32 | col)
// B split images, [k][n] row-major bf16 (wmma matrix_b row_major layout)
__device__ __nv_bfloat16  g_Bhi[128 * 128];
__device__ __nv_bfloat16  g_Blo[128 * 128];

// ---------------------------------------------------------------------------
// Prep: split W into hi/lo bf16 images, zero count/cursor, seed rowstart end.
// ---------------------------------------------------------------------------
__global__ void prep_kernel(const float* __restrict__ W) {
    int idx = blockIdx.x * blockDim.x + threadIdx.x;
    if (idx < 128 * 128) {
        float x = W[idx];                   // W is already [k][n]
        __nv_bfloat16 hi = __float2bfloat16(x);
        __nv_bfloat16 lo = __float2bfloat16(x - __bfloat162float(hi));
        g_Bhi[idx] = hi;
        g_Blo[idx] = lo;
    }
    if (idx < N_NODES) {
        g_count[idx] = 0;
        g_cursor[idx] = 0;
    }
    if (idx == 0) g_rowstart[N_NODES] = N_EDGES;  // scan total is a constant
}

// ---------------------------------------------------------------------------
// Persistent fused kernel: GEMM (split-bf16, B loaded once/CTA) + histogram.
// Epilogue converts fp32 accum -> fp16 support (halves downstream traffic).
// CTA: 256 threads = 8 warps, M-tile 64, warp tile 32x32. SMEM 104448 B.
// ---------------------------------------------------------------------------
#define STR 136
#define AHI_OFF 0
#define ALO_OFF (64 * STR)
#define BHI_OFF (128 * STR)
#define BLO_OFF (256 * STR)
#define SM_BYTES ((384 * STR) * 2)           // 104448
#define EPI_STRF 136                         // epilogue fp32 staging (A region)

__global__ __launch_bounds__(256, 2) void gemm_hist_kernel(const float* __restrict__ A,
                                                           const int* __restrict__ edge_row) {
    extern __shared__ __nv_bfloat16 sm[];
    float* smf = reinterpret_cast<float*>(sm);   // epilogue view (same bytes)
    const int tid = threadIdx.x;
    const int wid = tid >> 5;

    // --- Load B splits into SMEM ONCE. 8 uint4 per image/thread. ---
#pragma unroll
    for (int it = 0; it < 8; it++) {
        int v = it * 256 + tid;              // 0..2047
        int row = v >> 4;                    // 0..127
        int chunk = (v & 15) * 8;            // 0..120
        uint4 h = *reinterpret_cast<const uint4*>(g_Bhi + row * 128 + chunk);
        uint4 l = *reinterpret_cast<const uint4*>(g_Blo + row * 128 + chunk);
        *reinterpret_cast<uint4*>(sm + BHI_OFF + row * STR + chunk) = h;
        *reinterpret_cast<uint4*>(sm + BLO_OFF + row * STR + chunk) = l;
    }

    const int wm = (wid & 1) * 32;
    const int wn = (wid >> 1) * 32;

    for (int tile = blockIdx.x; tile < N_TILES; tile += gridDim.x) {
        const int blockM = tile * 64;

        __syncthreads();   // prior iter's epilogue SMEM reads done; B visible (1st iter)

        // --- Convert A tile fp32 -> (hi,lo) bf16 into SMEM. 8 float4/thread. ---
#pragma unroll
        for (int it = 0; it < 8; it++) {
            int linear = it * 256 + tid;     // 0..2047
            int row = linear >> 5;           // 0..63
            int kq = (linear & 31) << 2;     // 0,4,...,124
            int gr = blockM + row;
            float4 v = make_float4(0.f, 0.f, 0.f, 0.f);
            if (gr < N_NODES)
                v = *reinterpret_cast<const float4*>(A + (size_t)gr * D + kq);

            __nv_bfloat16 h0 = __float2bfloat16(v.x), h1 = __float2bfloat16(v.y);
            __nv_bfloat16 h2 = __float2bfloat16(v.z), h3 = __float2bfloat16(v.w);
            __nv_bfloat16 l0 = __float2bfloat16(v.x - __bfloat162float(h0));
            __nv_bfloat16 l1 = __float2bfloat16(v.y - __bfloat162float(h1));
            __nv_bfloat16 l2 = __float2bfloat16(v.z - __bfloat162float(h2));
            __nv_bfloat16 l3 = __float2bfloat16(v.w - __bfloat162float(h3));

            __nv_bfloat16* ah = sm + AHI_OFF + row * STR + kq;
            __nv_bfloat16* al = sm + ALO_OFF + row * STR + kq;
            *reinterpret_cast<__nv_bfloat162*>(ah)     = __nv_bfloat162(h0, h1);
            *reinterpret_cast<__nv_bfloat162*>(ah + 2) = __nv_bfloat162(h2, h3);
            *reinterpret_cast<__nv_bfloat162*>(al)     = __nv_bfloat162(l0, l1);
            *reinterpret_cast<__nv_bfloat162*>(al + 2) = __nv_bfloat162(l2, l3);
        }
        __syncthreads();

        // --- Warp-tiled MMA, 3 precision sweeps ---
        wmma::fragment<wmma::accumulator, 16, 16, 16, float> acc[2][2];
#pragma unroll
        for (int i = 0; i < 2; i++)
#pragma unroll
            for (int j = 0; j < 2; j++) wmma::fill_fragment(acc[i][j], 0.0f);

#pragma unroll
        for (int sweep = 0; sweep < 3; sweep++) {
            const __nv_bfloat16* As = sm + ((sweep == 2) ? ALO_OFF : AHI_OFF);
            const __nv_bfloat16* Bs = sm + ((sweep == 1) ? BLO_OFF : BHI_OFF);
#pragma unroll
            for (int k0 = 0; k0 < 128; k0 += 16) {
                wmma::fragment<wmma::matrix_a, 16, 16, 16, __nv_bfloat16, wmma::row_major> af[2];
                wmma::fragment<wmma::matrix_b, 16, 16, 16, __nv_bfloat16, wmma::row_major> bf[2];
#pragma unroll
                for (int i = 0; i < 2; i++)
                    wmma::load_matrix_sync(af[i], As + (wm + i * 16) * STR + k0, STR);
#pragma unroll
                for (int j = 0; j < 2; j++)
                    wmma::load_matrix_sync(bf[j], Bs + k0 * STR + wn + j * 16, STR);
#pragma unroll
                for (int i = 0; i < 2; i++)
#pragma unroll
                    for (int j = 0; j < 2; j++)
                        wmma::mma_sync(acc[i][j], af[i], bf[j], acc[i][j]);
            }
        }

        // --- Epilogue: stage fp32 in SMEM, convert to fp16, coalesced STG ---
        __syncthreads();     // all warps done reading A region
#pragma unroll
        for (int i = 0; i < 2; i++)
#pragma unroll
            for (int j = 0; j < 2; j++)
                wmma::store_matrix_sync(smf + (wm + i * 16) * EPI_STRF + wn + j * 16,
                                        acc[i][j], EPI_STRF, wmma::mem_row_major);
        __syncthreads();

        // 64 rows x 32 uint2 (4 halves each) = 2048; 8 per thread, coalesced.
#pragma unroll
        for (int it = 0; it < 8; it++) {
            int v = it * 256 + tid;          // 0..2047
            int row = v >> 5;                // 0..63
            int q = v & 31;                  // uint2 index in row
            const float* src = smf + row * EPI_STRF + q * 4;
            __half2 h0 = __floats2half2_rn(src[0], src[1]);
            __half2 h1 = __floats2half2_rn(src[2], src[3]);
            uint2 o;
            o.x = *reinterpret_cast<unsigned int*>(&h0);
            o.y = *reinterpret_cast<unsigned int*>(&h1);
            *(reinterpret_cast<uint2*>(g_support_h + (size_t)(tile * 64 + row) * 64) + q) = o;
        }
    }

    // --- Phase B: histogram (independent of GEMM output) ---
    for (int e = blockIdx.x * 256 + tid; e < N_EDGES; e += gridDim.x * 256)
        atomicAdd(&g_count[edge_row[e]], 1);
}

// ---------------------------------------------------------------------------
// Scan: per-block local scan, then addoff (block prefix computed in-kernel)
// ---------------------------------------------------------------------------
__global__ __launch_bounds__(SCAN_BLK) void scan_local_kernel() {
    __shared__ int warp_sums[32];
    const int tid = threadIdx.x;
    const int lane = tid & 31;
    const int wid = tid >> 5;
    const int i = blockIdx.x * SCAN_BLK + tid;

    int x = (i < N_NODES) ? g_count[i] : 0;
    int v = x;
#pragma unroll
    for (int o = 1; o < 32; o <<= 1) {
        int t = __shfl_up_sync(0xFFFFFFFFu, v, o);
        if (lane >= o) v += t;
    }
    if (lane == 31) warp_sums[wid] = v;
    __syncthreads();
    if (tid < 32) {
        int w = warp_sums[tid];
#pragma unroll
        for (int o = 1; o < 32; o <<= 1) {
            int t = __shfl_up_sync(0xFFFFFFFFu, w, o);
            if (tid >= o) w += t;
        }
        warp_sums[tid] = w;
    }
    __syncthreads();
    int incl = v + (wid > 0 ? warp_sums[wid - 1] : 0);
    if (i < N_NODES) g_rowstart[i] = incl - x;
    if (tid == SCAN_BLK - 1) g_blocksum[blockIdx.x] = incl;
}

// Each block computes its own prefix over the (<=98) block sums, then adds.
__global__ __launch_bounds__(SCAN_BLK) void scan_addoff_kernel() {
    __shared__ int s_off;
    const int tid = threadIdx.x;
    if (tid < 32) {
        int sum = 0;
        for (int b = tid; b < (int)blockIdx.x; b += 32) sum += g_blocksum[b];
#pragma unroll
        for (int o = 16; o > 0; o >>= 1) sum += __shfl_down_sync(0xFFFFFFFFu, sum, o);
        if (tid == 0) s_off = sum;
    }
    __syncthreads();
    const int i = blockIdx.x * SCAN_BLK + tid;
    if (i < N_NODES) g_rowstart[i] += s_off;
}

// Fill CSR as packed 8-byte (val,col) pairs: one scattered STG.64 per edge.
__global__ void fill_kernel(const float* __restrict__ edge_val,
                            const int* __restrict__ edge_row,
                            const int* __restrict__ edge_col) {
    int e = blockIdx.x * blockDim.x + threadIdx.x;
    if (e < N_EDGES) {
        int r = edge_row[e];
        int p = g_rowstart[r] + atomicAdd(&g_cursor[r], 1);
        long long pair = ((long long)(unsigned int)__float_as_uint(edge_val[e]) << 32)
                       | (unsigned int)edge_col[e];
        g_csr_pair[p] = pair;
    }
}

// ---------------------------------------------------------------------------
// Gather: one warp per row, TWO edges in flight per iteration.
// Lanes 0-15 process edge i, lanes 16-31 edge i+1. Each lane loads uint4
// (16 B = 8 halves) -> half-warp covers the 256 B fp16 row with LDG.128.
// Cross-half shfl_xor(16) reduction; lanes 0-15 store 2x float4.
// ---------------------------------------------------------------------------
__global__ __launch_bounds__(256) void gather_kernel(float* __restrict__ out) {
    int row = blockIdx.x * 8 + (threadIdx.x >> 5);
    int lane = threadIdx.x & 31;
    if (row >= N_NODES) return;

    int s = g_rowstart[row];
    int e = g_rowstart[row + 1];
    const int half = lane >> 4;          // 0 or 1
    const int l16 = lane & 15;

    float acc[8];
#pragma unroll
    for (int k = 0; k < 8; k++) acc[k] = 0.f;

#pragma unroll 2
    for (int i = s + half; i < e; i += 2) {
        long long pair = g_csr_pair[i];
        int c = (int)(unsigned int)(pair & 0xffffffffLL);
        float v = __uint_as_float((unsigned int)((unsigned long long)pair >> 32));
        uint4 hv = *(reinterpret_cast<const uint4*>(g_support_h + (size_t)c * 64) + l16);
        __half2 p0 = *reinterpret_cast<__half2*>(&hv.x);
        __half2 p1 = *reinterpret_cast<__half2*>(&hv.y);
        __half2 p2 = *reinterpret_cast<__half2*>(&hv.z);
        __half2 p3 = *reinterpret_cast<__half2*>(&hv.w);
        float2 f0 = __half22float2(p0);
        float2 f1 = __half22float2(p1);
        float2 f2 = __half22float2(p2);
        float2 f3 = __half22float2(p3);
        acc[0] = fmaf(v, f0.x, acc[0]);
        acc[1] = fmaf(v, f0.y, acc[1]);
        acc[2] = fmaf(v, f1.x, acc[2]);
        acc[3] = fmaf(v, f1.y, acc[3]);
        acc[4] = fmaf(v, f2.x, acc[4]);
        acc[5] = fmaf(v, f2.y, acc[5]);
        acc[6] = fmaf(v, f3.x, acc[6]);
        acc[7] = fmaf(v, f3.y, acc[7]);
    }

    // Combine the two half-warps (both accumulated the same 8 columns).
#pragma unroll
    for (int k = 0; k < 8; k++)
        acc[k] += __shfl_xor_sync(0xFFFFFFFFu, acc[k], 16);

    if (half == 0) {
        float4 o0, o1;
        o0.x = fmaxf(acc[0], 0.f); o0.y = fmaxf(acc[1], 0.f);
        o0.z = fmaxf(acc[2], 0.f); o0.w = fmaxf(acc[3], 0.f);
        o1.x = fmaxf(acc[4], 0.f); o1.y = fmaxf(acc[5], 0.f);
        o1.z = fmaxf(acc[6], 0.f); o1.w = fmaxf(acc[7], 0.f);
        float* dst = out + (size_t)row * D + l16 * 8;
        *reinterpret_cast<float4*>(dst)     = o0;
        *reinterpret_cast<float4*>(dst + 4) = o1;
    }
}

extern "C" void kernel_launch(void* const* d_in, const int* in_sizes, int n_in,
                              void* d_out, int out_size) {
    const float* features = (const float*)d_in[0];   // [100000, 128]
    const float* weight   = (const float*)d_in[1];   // [128, 128]
    const float* edge_val = (const float*)d_in[2];   // [1600000]
    const int*   edge_row = (const int*)d_in[3];     // [1600000]
    const int*   edge_col = (const int*)d_in[4];     // [1600000]
    float* out = (float*)d_out;                      // [100000, 128]

    cudaFuncSetAttribute(gemm_hist_kernel,
                         cudaFuncAttributeMaxDynamicSharedMemorySize, SM_BYTES);

    // 1) prep (B split + counter zeroing + rowstart end)
    prep_kernel<<<(N_NODES + 255) / 256, 256>>>(weight);

    // 2) persistent fused GEMM + histogram
    gemm_hist_kernel<<<GEMM_GRID, 256, SM_BYTES>>>(features, edge_row);

    // 3) scan + fill
    scan_local_kernel<<<N_SCAN_BLOCKS, SCAN_BLK>>>();
    scan_addoff_kernel<<<N_SCAN_BLOCKS, SCAN_BLK>>>();
    fill_kernel<<<(N_EDGES + 255) / 256, 256>>>(edge_val, edge_row, edge_col);

    // 4) fused gather + ReLU -> out
    gather_kernel<<<(N_NODES + 7) / 8, 256>>>(out);
}